// round 11
// baseline (speedup 1.0000x reference)
#include <cuda_runtime.h>
#include <cuda_bf16.h>
#include <math.h>
#include <stdint.h>

#define Bb 2
#define Ss 4096
#define Hh 2048
#define D2c 1024
#define SCALEF 0.125f

#define WSTRIDE ((size_t)Hh * 2 * Hh)        // one split weight matrix
#define QKSTRIDE ((size_t)Bb * Ss * 2 * Hh)  // one split activation tensor

// ---------------- static device scratch (allocation-free rule) --------------
__device__ __align__(256) float g_p  [(size_t)Bb*Ss*Ss];
__device__ __align__(256) __nv_bfloat16 g_hs2 [(size_t)Bb*Ss*2*Hh];
__device__ __align__(256) __nv_bfloat16 g_w2  [4 * WSTRIDE];          // q,k,v,o
__device__ __align__(256) __nv_bfloat16 g_qk2 [2 * QKSTRIDE];         // qr2, kr2
__device__ __align__(256) __nv_bfloat16 g_p2  [(size_t)Bb*Ss*2*Ss];
__device__ __align__(256) __nv_bfloat16 g_vt2 [(size_t)Bb*Hh*2*Ss];
__device__ __align__(256) __nv_bfloat16 g_ctx2[(size_t)Bb*Ss*2*Hh];

// ---------------- PTX helpers (portable: sm_80+ only) -----------------------
__device__ __forceinline__ uint32_t smem_u32(const void* p) {
    uint32_t a;
    asm("{ .reg .u64 t; cvta.to.shared.u64 t, %1; cvt.u32.u64 %0, t; }" : "=r"(a) : "l"(p));
    return a;
}
__device__ __forceinline__ void cp_async16(uint32_t dst, const void* src) {
    asm volatile("cp.async.cg.shared.global [%0], [%1], 16;" :: "r"(dst), "l"(src) : "memory");
}
#define CP_COMMIT() asm volatile("cp.async.commit_group;" ::: "memory")
#define CP_WAIT1()  asm volatile("cp.async.wait_group 1;" ::: "memory")
#define CP_WAIT0()  asm volatile("cp.async.wait_group 0;" ::: "memory")

__device__ __forceinline__ void ldsm_x4(uint32_t& r0, uint32_t& r1, uint32_t& r2, uint32_t& r3,
                                        uint32_t addr) {
    asm volatile("ldmatrix.sync.aligned.m8n8.x4.shared.b16 {%0,%1,%2,%3}, [%4];"
                 : "=r"(r0), "=r"(r1), "=r"(r2), "=r"(r3) : "r"(addr));
}
__device__ __forceinline__ void mma16816(float& d0, float& d1, float& d2, float& d3,
                                         uint32_t a0, uint32_t a1, uint32_t a2, uint32_t a3,
                                         uint32_t b0, uint32_t b1) {
    asm volatile("mma.sync.aligned.m16n8k16.row.col.f32.bf16.bf16.f32 "
                 "{%0,%1,%2,%3}, {%4,%5,%6,%7}, {%8,%9}, {%0,%1,%2,%3};"
                 : "+f"(d0), "+f"(d1), "+f"(d2), "+f"(d3)
                 : "r"(a0), "r"(a1), "r"(a2), "r"(a3), "r"(b0), "r"(b1));
}
__device__ __forceinline__ uint32_t swz(uint32_t b) { return b ^ ((b >> 3) & 0x70); }

__device__ __forceinline__ void split2(float x, __nv_bfloat16& h, __nv_bfloat16& l) {
    h = __float2bfloat16(x);
    l = __float2bfloat16(x - __bfloat162float(h));
}
__device__ __forceinline__ uint32_t pack2(__nv_bfloat16 a, __nv_bfloat16 b) {
    __nv_bfloat162 v(a, b);
    return *reinterpret_cast<uint32_t*>(&v);
}

// ---------------- mma.sync bf16 fused-3-product GEMM ------------------------
// C = alpha * (Ahi*Bhi + Alo*Bhi + Ahi*Blo)
// A2: [M x 2K] bf16 (hi cols [0,K), lo [K,2K)). B2: [N x 2K] same.
// Stage row (128 B): [hi 32 bf16 | lo 32 bf16], SW128 swizzle.
// CTA 128x256xBK32, 8 warps 2x4, warp tile 64x64, 1 CTA/SM.
// EPI: 0 = plain fp32 C (batch via z*sC)
//      2 = split only -> C2 (batch via z*sC)
//      3 = fused QKV: z=0 q->rope->C2; z=1 k->rope->C(out_k)+C2+QKSTRIDE;
//          z=2 v->plain fp32 C+sC (out_v). B2 selected via z*sB.
#define BM 128
#define BN 256
#define BK 32
#define STAGES 3
#define ATILE (BM * 128)                 // 16384 B
#define BTILE (BN * 128)                 // 32768 B
#define STAGE_BYTES (ATILE + BTILE)      // 49152 B
#define GSMEM (STAGES * STAGE_BYTES)     // 147456 B

__device__ __forceinline__ void load_chunk(
    const __nv_bfloat16* __restrict__ A2, const __nv_bfloat16* __restrict__ B2,
    uint32_t sb, int c, int K, long long K2, int m0, int n0, int tid)
{
    int k0 = c * BK;
    uint32_t bufA = sb + (uint32_t)(c % STAGES) * STAGE_BYTES;
    uint32_t bufB = bufA + ATILE;
    #pragma unroll
    for (int j = 0; j < 4; ++j) {
        int lin = tid + j * 256;
        int row = lin >> 3, ch = lin & 7;
        long long col = (ch < 4) ? (k0 + ch * 8) : ((long long)K + k0 + (ch - 4) * 8);
        cp_async16(bufA + swz(row * 128 + ch * 16),
                   A2 + (long long)(m0 + row) * K2 + col);
    }
    #pragma unroll
    for (int j = 0; j < 8; ++j) {
        int lin = tid + j * 256;
        int row = lin >> 3, ch = lin & 7;
        long long col = (ch < 4) ? (k0 + ch * 8) : ((long long)K + k0 + (ch - 4) * 8);
        cp_async16(bufB + swz(row * 128 + ch * 16),
                   B2 + (long long)(n0 + row) * K2 + col);
    }
}

template<int EPI>
__global__ void __launch_bounds__(256, 1)
gemm3f(const __nv_bfloat16* __restrict__ A2, const __nv_bfloat16* __restrict__ B2,
       float* __restrict__ C, __nv_bfloat16* __restrict__ C2,
       const float* __restrict__ cosb, const float* __restrict__ sinb,
       int M, int N, int K,
       long long sA, long long sB, long long sC, float alpha)
{
    extern __shared__ char smem[];
    uint32_t sb = smem_u32(smem);
    const int tid = threadIdx.x;
    const int wid = tid >> 5, lane = tid & 31;
    const int wm = wid & 1;      // 2 warps along M: 64 rows
    const int wn = wid >> 1;     // 4 warps along N: 64 cols
    const int z = blockIdx.z;
    A2 += (long long)z * sA;
    B2 += (long long)z * sB;
    if (EPI == 0) C += (long long)z * sC;
    if (EPI == 2) C2 += (long long)z * sC;
    const int m0 = blockIdx.y * BM, n0 = blockIdx.x * BN;
    const long long K2 = 2LL * K;
    const int nchunks = K / BK;

    float acc[4][8][4];
    #pragma unroll
    for (int i = 0; i < 4; ++i)
        #pragma unroll
        for (int j = 0; j < 8; ++j)
            #pragma unroll
            for (int q = 0; q < 4; ++q) acc[i][j][q] = 0.f;

    const int lrow = lane & 15;
    const int lhalf = lane >> 4;

    load_chunk(A2, B2, sb, 0, K, K2, m0, n0, tid); CP_COMMIT();
    load_chunk(A2, B2, sb, 1, K, K2, m0, n0, tid); CP_COMMIT();

    for (int c = 0; c < nchunks; ++c) {
        if (c + 1 < nchunks) { CP_WAIT1(); } else { CP_WAIT0(); }
        __syncthreads();
        if (c + 2 < nchunks) {
            load_chunk(A2, B2, sb, c + 2, K, K2, m0, n0, tid);
            CP_COMMIT();
        }
        uint32_t aBase = sb + (uint32_t)(c % STAGES) * STAGE_BYTES;
        uint32_t bBase = aBase + ATILE;
        #pragma unroll
        for (int ks = 0; ks < BK / 16; ++ks) {
            int chh = ks * 2 + lhalf;
            int chl = 4 + ks * 2 + lhalf;
            uint32_t ah[4][4], al[4][4], bh[8][2], bl[8][2];
            #pragma unroll
            for (int im = 0; im < 4; ++im) {
                int row = wm * 64 + im * 16 + lrow;
                uint32_t rb = aBase + row * 128;
                int sx = row & 7;
                ldsm_x4(ah[im][0], ah[im][1], ah[im][2], ah[im][3], rb + ((chh ^ sx) * 16));
                ldsm_x4(al[im][0], al[im][1], al[im][2], al[im][3], rb + ((chl ^ sx) * 16));
            }
            #pragma unroll
            for (int ib = 0; ib < 4; ++ib) {
                int row = wn * 64 + ib * 16 + lrow;
                uint32_t rb = bBase + row * 128;
                int sx = row & 7;
                ldsm_x4(bh[2*ib][0], bh[2*ib+1][0], bh[2*ib][1], bh[2*ib+1][1], rb + ((chh ^ sx) * 16));
                ldsm_x4(bl[2*ib][0], bl[2*ib+1][0], bl[2*ib][1], bl[2*ib+1][1], rb + ((chl ^ sx) * 16));
            }
            // product-major ordering: long accumulator reuse distance
            #pragma unroll
            for (int im = 0; im < 4; ++im)
                #pragma unroll
                for (int in = 0; in < 8; ++in)
                    mma16816(acc[im][in][0], acc[im][in][1], acc[im][in][2], acc[im][in][3],
                             ah[im][0], ah[im][1], ah[im][2], ah[im][3], bh[in][0], bh[in][1]);
            #pragma unroll
            for (int im = 0; im < 4; ++im)
                #pragma unroll
                for (int in = 0; in < 8; ++in)
                    mma16816(acc[im][in][0], acc[im][in][1], acc[im][in][2], acc[im][in][3],
                             al[im][0], al[im][1], al[im][2], al[im][3], bh[in][0], bh[in][1]);
            #pragma unroll
            for (int im = 0; im < 4; ++im)
                #pragma unroll
                for (int in = 0; in < 8; ++in)
                    mma16816(acc[im][in][0], acc[im][in][1], acc[im][in][2], acc[im][in][3],
                             ah[im][0], ah[im][1], ah[im][2], ah[im][3], bl[in][0], bl[in][1]);
        }
    }
    __syncthreads();

    const int r0 = lane >> 2;
    const int cc = (lane & 3) * 2;
    const long long N2 = 2LL * N;
    #pragma unroll
    for (int im = 0; im < 4; ++im) {
        #pragma unroll
        for (int in = 0; in < 8; ++in) {
            long long m = m0 + wm * 64 + im * 16 + r0;
            long long n = n0 + wn * 64 + in * 8 + cc;
            float v0 = acc[im][in][0] * alpha, v1 = acc[im][in][1] * alpha;
            float v2 = acc[im][in][2] * alpha, v3 = acc[im][in][3] * alpha;
            if (EPI == 0) {
                *(float2*)&C[m * N + n]       = make_float2(v0, v1);
                *(float2*)&C[(m + 8) * N + n] = make_float2(v2, v3);
            } else if (EPI == 2) {
                __nv_bfloat16 h0,l0,h1,l1,h2,l2,h3,l3;
                split2(v0,h0,l0); split2(v1,h1,l1); split2(v2,h2,l2); split2(v3,h3,l3);
                uint32_t* c2p = (uint32_t*)C2;
                c2p[(m * N2 + n) >> 1]           = pack2(h0, h1);
                c2p[(m * N2 + N + n) >> 1]       = pack2(l0, l1);
                c2p[((m + 8) * N2 + n) >> 1]     = pack2(h2, h3);
                c2p[((m + 8) * N2 + N + n) >> 1] = pack2(l2, l3);
            } else { // EPI == 3: fused QKV
                if (z == 2) {
                    float* Cv = C + sC;    // out_v
                    *(float2*)&Cv[m * N + n]       = make_float2(v0, v1);
                    *(float2*)&Cv[(m + 8) * N + n] = make_float2(v2, v3);
                } else {
                    int i = (int)(n >> 1);
                    int s1 = (int)(m & (Ss - 1));
                    int s2 = (int)((m + 8) & (Ss - 1));
                    float c1 = cosb[(size_t)s1 * D2c + i], sn1 = sinb[(size_t)s1 * D2c + i];
                    float c2 = cosb[(size_t)s2 * D2c + i], sn2 = sinb[(size_t)s2 * D2c + i];
                    float o0 = v0 * c1 - v1 * sn1, o1 = v0 * sn1 + v1 * c1;
                    float o2 = v2 * c2 - v3 * sn2, o3 = v2 * sn2 + v3 * c2;
                    if (z == 1) {   // k: fp32 out_k
                        *(float2*)&C[m * N + n]       = make_float2(o0, o1);
                        *(float2*)&C[(m + 8) * N + n] = make_float2(o2, o3);
                    }
                    __nv_bfloat16 h0,l0,h1,l1,h2,l2,h3,l3;
                    split2(o0,h0,l0); split2(o1,h1,l1); split2(o2,h2,l2); split2(o3,h3,l3);
                    uint32_t* c2p = (uint32_t*)(C2 + (size_t)z * QKSTRIDE);
                    c2p[(m * N2 + n) >> 1]           = pack2(h0, h1);
                    c2p[(m * N2 + N + n) >> 1]       = pack2(l0, l1);
                    c2p[((m + 8) * N2 + n) >> 1]     = pack2(h2, h3);
                    c2p[((m + 8) * N2 + N + n) >> 1] = pack2(l2, l3);
                }
            }
        }
    }
}

// ---------------- elementwise kernels ----------------------------------------
__global__ void __launch_bounds__(256)
convert_split4(const float* __restrict__ in, __nv_bfloat16* __restrict__ out)
{
    size_t idx = (size_t)blockIdx.x * 256 + threadIdx.x;
    size_t r = idx >> 9; int c4 = (int)(idx & 511);
    float4 v = *(const float4*)&in[(r << 11) + c4 * 4];
    __nv_bfloat16 h0,l0,h1,l1,h2,l2,h3,l3;
    split2(v.x,h0,l0); split2(v.y,h1,l1); split2(v.z,h2,l2); split2(v.w,h3,l3);
    *(uint2*)&out[(r << 12) + c4 * 4]        = make_uint2(pack2(h0,h1), pack2(h2,h3));
    *(uint2*)&out[(r << 12) + 2048 + c4 * 4] = make_uint2(pack2(l0,l1), pack2(l2,l3));
}

__global__ void __launch_bounds__(256)
convert_weights(const float* __restrict__ wq, const float* __restrict__ wk,
                const float* __restrict__ wv, const float* __restrict__ wo,
                __nv_bfloat16* __restrict__ outbase)
{
    int zz = blockIdx.z;
    const float* in = (zz == 0) ? wq : (zz == 1) ? wk : (zz == 2) ? wv : wo;
    __nv_bfloat16* out = outbase + (size_t)zz * WSTRIDE;
    size_t idx = (size_t)blockIdx.x * 256 + threadIdx.x;
    size_t j = idx >> 9; int c4 = (int)(idx & 511);
    size_t pj = (zz < 2) ? ((j & 1) ? (1024 + (j >> 1)) : (j >> 1)) : j;
    float4 v = *(const float4*)&in[(pj << 11) + c4 * 4];
    __nv_bfloat16 h0,l0,h1,l1,h2,l2,h3,l3;
    split2(v.x,h0,l0); split2(v.y,h1,l1); split2(v.z,h2,l2); split2(v.w,h3,l3);
    *(uint2*)&out[(j << 12) + c4 * 4]        = make_uint2(pack2(h0,h1), pack2(h2,h3));
    *(uint2*)&out[(j << 12) + 2048 + c4 * 4] = make_uint2(pack2(l0,l1), pack2(l2,l3));
}

__global__ void transpose_split(const float* __restrict__ v, __nv_bfloat16* __restrict__ vt2)
{
    __shared__ float t[32][33];
    int b = blockIdx.z;
    int n0 = blockIdx.x * 32, k0 = blockIdx.y * 32;
    const float* vb = v + (size_t)b * Ss * Hh;
    __nv_bfloat16* ob = vt2 + (size_t)b * Hh * 2 * Ss;
    int tx = threadIdx.x, ty0 = threadIdx.y;
    #pragma unroll
    for (int r = 0; r < 4; ++r) {
        int ty = ty0 + r * 8;
        t[ty][tx] = vb[(size_t)(k0 + ty) * Hh + n0 + tx];
    }
    __syncthreads();
    #pragma unroll
    for (int r = 0; r < 4; ++r) {
        int ty = ty0 + r * 8;
        __nv_bfloat16 h, l; split2(t[tx][ty], h, l);
        size_t o = (size_t)(n0 + ty) * (2 * Ss) + k0 + tx;
        ob[o] = h; ob[o + Ss] = l;
    }
}

__global__ void __launch_bounds__(256)
softmax_split(const float* __restrict__ P, __nv_bfloat16* __restrict__ P2)
{
    const float* row = P + (size_t)blockIdx.x * Ss;
    __nv_bfloat16* orow = P2 + (size_t)blockIdx.x * (2 * Ss);
    int tid = threadIdx.x;
    float e[16];
    __shared__ float red[256];
    float m = -INFINITY;
    #pragma unroll
    for (int j4 = 0; j4 < 4; ++j4) {
        float4 v = *(const float4*)&row[tid * 16 + j4 * 4];
        e[j4*4+0]=v.x; e[j4*4+1]=v.y; e[j4*4+2]=v.z; e[j4*4+3]=v.w;
        m = fmaxf(m, fmaxf(fmaxf(v.x, v.y), fmaxf(v.z, v.w)));
    }
    red[tid] = m; __syncthreads();
    for (int s = 128; s > 0; s >>= 1) {
        if (tid < s) red[tid] = fmaxf(red[tid], red[tid + s]);
        __syncthreads();
    }
    m = red[0]; __syncthreads();
    float sum = 0.f;
    #pragma unroll
    for (int j = 0; j < 16; ++j) { e[j] = __expf(e[j] - m); sum += e[j]; }
    red[tid] = sum; __syncthreads();
    for (int s = 128; s > 0; s >>= 1) {
        if (tid < s) red[tid] += red[tid + s];
        __syncthreads();
    }
    float inv = 1.f / red[0];
    __nv_bfloat16 h[16], l[16];
    #pragma unroll
    for (int j = 0; j < 16; ++j) split2(e[j] * inv, h[j], l[j]);
    *(uint4*)&orow[tid * 16]          = make_uint4(pack2(h[0],h[1]), pack2(h[2],h[3]), pack2(h[4],h[5]), pack2(h[6],h[7]));
    *(uint4*)&orow[tid * 16 + 8]      = make_uint4(pack2(h[8],h[9]), pack2(h[10],h[11]), pack2(h[12],h[13]), pack2(h[14],h[15]));
    *(uint4*)&orow[Ss + tid * 16]     = make_uint4(pack2(l[0],l[1]), pack2(l[2],l[3]), pack2(l[4],l[5]), pack2(l[6],l[7]));
    *(uint4*)&orow[Ss + tid * 16 + 8] = make_uint4(pack2(l[8],l[9]), pack2(l[10],l[11]), pack2(l[12],l[13]), pack2(l[14],l[15]));
}

// ---------------- launch ----------------------------------------------------
extern "C" void kernel_launch(void* const* d_in, const int* in_sizes, int n_in,
                              void* d_out, int out_size)
{
    const float* hs   = (const float*)d_in[0];
    const float* wq   = (const float*)d_in[1];
    const float* wk   = (const float*)d_in[2];
    const float* wv   = (const float*)d_in[3];
    const float* wo   = (const float*)d_in[4];
    const float* fcos = (const float*)d_in[5];
    const float* fsin = (const float*)d_in[6];

    float* out = (float*)d_out;
    const long long T = (long long)Bb * Ss * Hh;
    float* out_o = out;
    float* out_k = out + T;
    float* out_v = out + 2 * T;

    float *p;
    __nv_bfloat16 *hs2, *w2, *qk2, *p2, *vt2, *ctx2;
    cudaGetSymbolAddress((void**)&p,    g_p);
    cudaGetSymbolAddress((void**)&hs2,  g_hs2);
    cudaGetSymbolAddress((void**)&w2,   g_w2);
    cudaGetSymbolAddress((void**)&qk2,  g_qk2);
    cudaGetSymbolAddress((void**)&p2,   g_p2);
    cudaGetSymbolAddress((void**)&vt2,  g_vt2);
    cudaGetSymbolAddress((void**)&ctx2, g_ctx2);

    cudaFuncSetAttribute(gemm3f<0>, cudaFuncAttributeMaxDynamicSharedMemorySize, GSMEM);
    cudaFuncSetAttribute(gemm3f<2>, cudaFuncAttributeMaxDynamicSharedMemorySize, GSMEM);
    cudaFuncSetAttribute(gemm3f<3>, cudaFuncAttributeMaxDynamicSharedMemorySize, GSMEM);

    dim3 blk(256);
    // input splits
    convert_split4<<<(unsigned)((size_t)Bb*Ss*Hh/1024), blk>>>(hs, hs2);
    convert_weights<<<dim3((unsigned)((size_t)Hh*Hh/1024), 1, 4), blk>>>(wq, wk, wv, wo, w2);

    // fused QKV projections (z = 0:q, 1:k, 2:v), RoPE in epilogue for q/k
    dim3 gqkv(Hh / BN, (Bb * Ss) / BM, 3);
    gemm3f<3><<<gqkv, 256, GSMEM>>>(hs2, w2, out_k, qk2, fcos, fsin,
                                    Bb*Ss, Hh, Hh,
                                    0, (long long)WSTRIDE, T, 1.f);

    // v transpose+split
    dim3 gtr(Hh / 32, Ss / 32, Bb);
    transpose_split<<<gtr, dim3(32, 8)>>>(out_v, vt2);

    // scores = 0.125 * Qr @ Kr^T (per batch)
    dim3 gsc(Ss / BN, Ss / BM, Bb);
    gemm3f<0><<<gsc, 256, GSMEM>>>(qk2, qk2 + QKSTRIDE, p, nullptr, nullptr, nullptr,
                                   Ss, Ss, Hh,
                                   (long long)Ss*2*Hh, (long long)Ss*2*Hh,
                                   (long long)Ss*Ss, SCALEF);

    // softmax + split
    softmax_split<<<Bb * Ss, blk>>>(p, p2);

    // ctx = P @ V (per batch), split fused -> ctx2
    dim3 gcx(Hh / BN, Ss / BM, Bb);
    gemm3f<2><<<gcx, 256, GSMEM>>>(p2, vt2, nullptr, ctx2, nullptr, nullptr,
                                   Ss, Hh, Ss,
                                   (long long)Ss*2*Ss, (long long)Hh*2*Ss,
                                   (long long)Ss*2*Hh, 1.f);

    // output projection
    dim3 gop(Hh / BN, (Bb * Ss) / BM, 1);
    gemm3f<0><<<gop, 256, GSMEM>>>(ctx2, w2 + 3 * WSTRIDE, out_o, nullptr, nullptr, nullptr,
                                   Bb*Ss, Hh, Hh, 0, 0, 0, 1.f);
}

// round 12
// speedup vs baseline: 1.1119x; 1.1119x over previous
#include <cuda_runtime.h>
#include <cuda_bf16.h>
#include <math.h>
#include <stdint.h>

#define Bb 2
#define Ss 4096
#define Hh 2048
#define D2c 1024
#define SCALEF 0.125f

#define WSTRIDE ((size_t)Hh * 2 * Hh)        // one split weight matrix
#define QKSTRIDE ((size_t)Bb * Ss * 2 * Hh)  // one split activation tensor

// ---------------- static device scratch (allocation-free rule) --------------
__device__ __align__(256) float g_p  [(size_t)Bb*Ss*Ss];
__device__ __align__(256) __nv_bfloat16 g_hs2 [(size_t)Bb*Ss*2*Hh];
__device__ __align__(256) __nv_bfloat16 g_w2  [4 * WSTRIDE];          // q,k,v,o
__device__ __align__(256) __nv_bfloat16 g_qk2 [2 * QKSTRIDE];         // qr2, kr2
__device__ __align__(256) __nv_bfloat16 g_p2  [(size_t)Bb*Ss*2*Ss];
__device__ __align__(256) __nv_bfloat16 g_vt2 [(size_t)Bb*Hh*2*Ss];
__device__ __align__(256) __nv_bfloat16 g_ctx2[(size_t)Bb*Ss*2*Hh];

// ---------------- PTX helpers (portable: sm_80+ only) -----------------------
__device__ __forceinline__ uint32_t smem_u32(const void* p) {
    uint32_t a;
    asm("{ .reg .u64 t; cvta.to.shared.u64 t, %1; cvt.u32.u64 %0, t; }" : "=r"(a) : "l"(p));
    return a;
}
__device__ __forceinline__ void cp_async16(uint32_t dst, const void* src) {
    asm volatile("cp.async.cg.shared.global [%0], [%1], 16;" :: "r"(dst), "l"(src) : "memory");
}
#define CP_COMMIT() asm volatile("cp.async.commit_group;" ::: "memory")
#define CP_WAIT1()  asm volatile("cp.async.wait_group 1;" ::: "memory")
#define CP_WAIT0()  asm volatile("cp.async.wait_group 0;" ::: "memory")

__device__ __forceinline__ void ldsm_x4(uint32_t& r0, uint32_t& r1, uint32_t& r2, uint32_t& r3,
                                        uint32_t addr) {
    asm volatile("ldmatrix.sync.aligned.m8n8.x4.shared.b16 {%0,%1,%2,%3}, [%4];"
                 : "=r"(r0), "=r"(r1), "=r"(r2), "=r"(r3) : "r"(addr));
}
__device__ __forceinline__ void mma16816(float& d0, float& d1, float& d2, float& d3,
                                         uint32_t a0, uint32_t a1, uint32_t a2, uint32_t a3,
                                         uint32_t b0, uint32_t b1) {
    asm volatile("mma.sync.aligned.m16n8k16.row.col.f32.bf16.bf16.f32 "
                 "{%0,%1,%2,%3}, {%4,%5,%6,%7}, {%8,%9}, {%0,%1,%2,%3};"
                 : "+f"(d0), "+f"(d1), "+f"(d2), "+f"(d3)
                 : "r"(a0), "r"(a1), "r"(a2), "r"(a3), "r"(b0), "r"(b1));
}
__device__ __forceinline__ uint32_t swz(uint32_t b) { return b ^ ((b >> 3) & 0x70); }

__device__ __forceinline__ void split2(float x, __nv_bfloat16& h, __nv_bfloat16& l) {
    h = __float2bfloat16(x);
    l = __float2bfloat16(x - __bfloat162float(h));
}
__device__ __forceinline__ uint32_t pack2(__nv_bfloat16 a, __nv_bfloat16 b) {
    __nv_bfloat162 v(a, b);
    return *reinterpret_cast<uint32_t*>(&v);
}

// ---------------- mma.sync bf16 fused-3-product GEMM ------------------------
// C = alpha * (Ahi*Bhi + Alo*Bhi + Ahi*Blo)
// A2: [M x 2K] bf16 (hi cols [0,K), lo [K,2K)). B2: [N x 2K] same.
// Stage row (128 B): [hi 32 bf16 | lo 32 bf16], SW128 swizzle.
// CTA 128x128xBK32, 4 warps 2x2, warp tile 64x64, 2 CTAs/SM. (R10 geometry)
// Inner step interleaves: ldsm(hi) -> hh MMAs (hides ldsm(lo)) -> lh, hl MMAs.
// EPI: 0 = plain fp32 C (batch via z*sC)
//      2 = split only -> C2 (batch via z*sC)
//      3 = fused QKV: z=0 q->rope->C2; z=1 k->rope->C(out_k)+C2+QKSTRIDE;
//          z=2 v->plain fp32 C+sC (out_v). B2 selected via z*sB.
#define BM 128
#define BN 128
#define BK 32
#define STAGES 3
#define ATILE (BM * 128)
#define STAGE_BYTES (2 * ATILE)
#define GSMEM (STAGES * STAGE_BYTES)   // 98304 B

__device__ __forceinline__ void load_chunk(
    const __nv_bfloat16* __restrict__ A2, const __nv_bfloat16* __restrict__ B2,
    uint32_t sb, int c, int K, long long K2, int m0, int n0, int tid)
{
    int k0 = c * BK;
    uint32_t bufA = sb + (uint32_t)(c % STAGES) * STAGE_BYTES;
    uint32_t bufB = bufA + ATILE;
    #pragma unroll
    for (int j = 0; j < 8; ++j) {
        int lin = tid + j * 128;
        int row = lin >> 3, ch = lin & 7;
        long long col = (ch < 4) ? (k0 + ch * 8) : ((long long)K + k0 + (ch - 4) * 8);
        cp_async16(bufA + swz(row * 128 + ch * 16),
                   A2 + (long long)(m0 + row) * K2 + col);
    }
    #pragma unroll
    for (int j = 0; j < 8; ++j) {
        int lin = tid + j * 128;
        int row = lin >> 3, ch = lin & 7;
        long long col = (ch < 4) ? (k0 + ch * 8) : ((long long)K + k0 + (ch - 4) * 8);
        cp_async16(bufB + swz(row * 128 + ch * 16),
                   B2 + (long long)(n0 + row) * K2 + col);
    }
}

template<int EPI>
__global__ void __launch_bounds__(128, 2)
gemm3f(const __nv_bfloat16* __restrict__ A2, const __nv_bfloat16* __restrict__ B2,
       float* __restrict__ C, __nv_bfloat16* __restrict__ C2,
       const float* __restrict__ cosb, const float* __restrict__ sinb,
       int M, int N, int K,
       long long sA, long long sB, long long sC, float alpha)
{
    extern __shared__ char smem[];
    uint32_t sb = smem_u32(smem);
    const int tid = threadIdx.x;
    const int wid = tid >> 5, lane = tid & 31;
    const int wm = wid & 1;      // 2 warps along M: 64 rows
    const int wn = wid >> 1;     // 2 warps along N: 64 cols
    const int z = blockIdx.z;
    A2 += (long long)z * sA;
    B2 += (long long)z * sB;
    if (EPI == 0) C += (long long)z * sC;
    if (EPI == 2) C2 += (long long)z * sC;
    const int m0 = blockIdx.y * BM, n0 = blockIdx.x * BN;
    const long long K2 = 2LL * K;
    const int nchunks = K / BK;

    float acc[4][8][4];
    #pragma unroll
    for (int i = 0; i < 4; ++i)
        #pragma unroll
        for (int j = 0; j < 8; ++j)
            #pragma unroll
            for (int q = 0; q < 4; ++q) acc[i][j][q] = 0.f;

    const int lrow = lane & 15;
    const int lhalf = lane >> 4;

    load_chunk(A2, B2, sb, 0, K, K2, m0, n0, tid); CP_COMMIT();
    load_chunk(A2, B2, sb, 1, K, K2, m0, n0, tid); CP_COMMIT();

    for (int c = 0; c < nchunks; ++c) {
        if (c + 1 < nchunks) { CP_WAIT1(); } else { CP_WAIT0(); }
        __syncthreads();
        if (c + 2 < nchunks) {
            load_chunk(A2, B2, sb, c + 2, K, K2, m0, n0, tid);
            CP_COMMIT();
        }
        uint32_t aBase = sb + (uint32_t)(c % STAGES) * STAGE_BYTES;
        uint32_t bBase = aBase + ATILE;
        #pragma unroll
        for (int ks = 0; ks < BK / 16; ++ks) {
            int chh = ks * 2 + lhalf;
            int chl = 4 + ks * 2 + lhalf;
            uint32_t ah[4][4], al[4][4], bh[8][2], bl[8][2];
            // --- load hi fragments only ---
            #pragma unroll
            for (int im = 0; im < 4; ++im) {
                int row = wm * 64 + im * 16 + lrow;
                uint32_t rb = aBase + row * 128;
                int sx = row & 7;
                ldsm_x4(ah[im][0], ah[im][1], ah[im][2], ah[im][3], rb + ((chh ^ sx) * 16));
            }
            #pragma unroll
            for (int ib = 0; ib < 4; ++ib) {
                int row = wn * 64 + ib * 16 + lrow;
                uint32_t rb = bBase + row * 128;
                int sx = row & 7;
                ldsm_x4(bh[2*ib][0], bh[2*ib+1][0], bh[2*ib][1], bh[2*ib+1][1], rb + ((chh ^ sx) * 16));
            }
            // --- hh MMAs (cover lo LDSM latency issued below) ---
            #pragma unroll
            for (int im = 0; im < 4; ++im)
                #pragma unroll
                for (int in = 0; in < 8; ++in)
                    mma16816(acc[im][in][0], acc[im][in][1], acc[im][in][2], acc[im][in][3],
                             ah[im][0], ah[im][1], ah[im][2], ah[im][3], bh[in][0], bh[in][1]);
            // --- load lo fragments ---
            #pragma unroll
            for (int im = 0; im < 4; ++im) {
                int row = wm * 64 + im * 16 + lrow;
                uint32_t rb = aBase + row * 128;
                int sx = row & 7;
                ldsm_x4(al[im][0], al[im][1], al[im][2], al[im][3], rb + ((chl ^ sx) * 16));
            }
            #pragma unroll
            for (int ib = 0; ib < 4; ++ib) {
                int row = wn * 64 + ib * 16 + lrow;
                uint32_t rb = bBase + row * 128;
                int sx = row & 7;
                ldsm_x4(bl[2*ib][0], bl[2*ib+1][0], bl[2*ib][1], bl[2*ib+1][1], rb + ((chl ^ sx) * 16));
            }
            // --- lh + hl MMAs ---
            #pragma unroll
            for (int im = 0; im < 4; ++im)
                #pragma unroll
                for (int in = 0; in < 8; ++in)
                    mma16816(acc[im][in][0], acc[im][in][1], acc[im][in][2], acc[im][in][3],
                             al[im][0], al[im][1], al[im][2], al[im][3], bh[in][0], bh[in][1]);
            #pragma unroll
            for (int im = 0; im < 4; ++im)
                #pragma unroll
                for (int in = 0; in < 8; ++in)
                    mma16816(acc[im][in][0], acc[im][in][1], acc[im][in][2], acc[im][in][3],
                             ah[im][0], ah[im][1], ah[im][2], ah[im][3], bl[in][0], bl[in][1]);
        }
    }
    __syncthreads();

    const int r0 = lane >> 2;
    const int cc = (lane & 3) * 2;
    const long long N2 = 2LL * N;
    #pragma unroll
    for (int im = 0; im < 4; ++im) {
        #pragma unroll
        for (int in = 0; in < 8; ++in) {
            long long m = m0 + wm * 64 + im * 16 + r0;
            long long n = n0 + wn * 64 + in * 8 + cc;
            float v0 = acc[im][in][0] * alpha, v1 = acc[im][in][1] * alpha;
            float v2 = acc[im][in][2] * alpha, v3 = acc[im][in][3] * alpha;
            if (EPI == 0) {
                *(float2*)&C[m * N + n]       = make_float2(v0, v1);
                *(float2*)&C[(m + 8) * N + n] = make_float2(v2, v3);
            } else if (EPI == 2) {
                __nv_bfloat16 h0,l0,h1,l1,h2,l2,h3,l3;
                split2(v0,h0,l0); split2(v1,h1,l1); split2(v2,h2,l2); split2(v3,h3,l3);
                uint32_t* c2p = (uint32_t*)C2;
                c2p[(m * N2 + n) >> 1]           = pack2(h0, h1);
                c2p[(m * N2 + N + n) >> 1]       = pack2(l0, l1);
                c2p[((m + 8) * N2 + n) >> 1]     = pack2(h2, h3);
                c2p[((m + 8) * N2 + N + n) >> 1] = pack2(l2, l3);
            } else { // EPI == 3: fused QKV
                if (z == 2) {
                    float* Cv = C + sC;    // out_v
                    *(float2*)&Cv[m * N + n]       = make_float2(v0, v1);
                    *(float2*)&Cv[(m + 8) * N + n] = make_float2(v2, v3);
                } else {
                    int i = (int)(n >> 1);
                    int s1 = (int)(m & (Ss - 1));
                    int s2 = (int)((m + 8) & (Ss - 1));
                    float c1 = cosb[(size_t)s1 * D2c + i], sn1 = sinb[(size_t)s1 * D2c + i];
                    float c2 = cosb[(size_t)s2 * D2c + i], sn2 = sinb[(size_t)s2 * D2c + i];
                    float o0 = v0 * c1 - v1 * sn1, o1 = v0 * sn1 + v1 * c1;
                    float o2 = v2 * c2 - v3 * sn2, o3 = v2 * sn2 + v3 * c2;
                    if (z == 1) {   // k: fp32 out_k
                        *(float2*)&C[m * N + n]       = make_float2(o0, o1);
                        *(float2*)&C[(m + 8) * N + n] = make_float2(o2, o3);
                    }
                    __nv_bfloat16 h0,l0,h1,l1,h2,l2,h3,l3;
                    split2(o0,h0,l0); split2(o1,h1,l1); split2(o2,h2,l2); split2(o3,h3,l3);
                    uint32_t* c2p = (uint32_t*)(C2 + (size_t)z * QKSTRIDE);
                    c2p[(m * N2 + n) >> 1]           = pack2(h0, h1);
                    c2p[(m * N2 + N + n) >> 1]       = pack2(l0, l1);
                    c2p[((m + 8) * N2 + n) >> 1]     = pack2(h2, h3);
                    c2p[((m + 8) * N2 + N + n) >> 1] = pack2(l2, l3);
                }
            }
        }
    }
}

// ---------------- elementwise kernels ----------------------------------------
__global__ void __launch_bounds__(256)
convert_split4(const float* __restrict__ in, __nv_bfloat16* __restrict__ out)
{
    size_t idx = (size_t)blockIdx.x * 256 + threadIdx.x;
    size_t r = idx >> 9; int c4 = (int)(idx & 511);
    float4 v = *(const float4*)&in[(r << 11) + c4 * 4];
    __nv_bfloat16 h0,l0,h1,l1,h2,l2,h3,l3;
    split2(v.x,h0,l0); split2(v.y,h1,l1); split2(v.z,h2,l2); split2(v.w,h3,l3);
    *(uint2*)&out[(r << 12) + c4 * 4]        = make_uint2(pack2(h0,h1), pack2(h2,h3));
    *(uint2*)&out[(r << 12) + 2048 + c4 * 4] = make_uint2(pack2(l0,l1), pack2(l2,l3));
}

__global__ void __launch_bounds__(256)
convert_weights(const float* __restrict__ wq, const float* __restrict__ wk,
                const float* __restrict__ wv, const float* __restrict__ wo,
                __nv_bfloat16* __restrict__ outbase)
{
    int zz = blockIdx.z;
    const float* in = (zz == 0) ? wq : (zz == 1) ? wk : (zz == 2) ? wv : wo;
    __nv_bfloat16* out = outbase + (size_t)zz * WSTRIDE;
    size_t idx = (size_t)blockIdx.x * 256 + threadIdx.x;
    size_t j = idx >> 9; int c4 = (int)(idx & 511);
    size_t pj = (zz < 2) ? ((j & 1) ? (1024 + (j >> 1)) : (j >> 1)) : j;
    float4 v = *(const float4*)&in[(pj << 11) + c4 * 4];
    __nv_bfloat16 h0,l0,h1,l1,h2,l2,h3,l3;
    split2(v.x,h0,l0); split2(v.y,h1,l1); split2(v.z,h2,l2); split2(v.w,h3,l3);
    *(uint2*)&out[(j << 12) + c4 * 4]        = make_uint2(pack2(h0,h1), pack2(h2,h3));
    *(uint2*)&out[(j << 12) + 2048 + c4 * 4] = make_uint2(pack2(l0,l1), pack2(l2,l3));
}

__global__ void transpose_split(const float* __restrict__ v, __nv_bfloat16* __restrict__ vt2)
{
    __shared__ float t[32][33];
    int b = blockIdx.z;
    int n0 = blockIdx.x * 32, k0 = blockIdx.y * 32;
    const float* vb = v + (size_t)b * Ss * Hh;
    __nv_bfloat16* ob = vt2 + (size_t)b * Hh * 2 * Ss;
    int tx = threadIdx.x, ty0 = threadIdx.y;
    #pragma unroll
    for (int r = 0; r < 4; ++r) {
        int ty = ty0 + r * 8;
        t[ty][tx] = vb[(size_t)(k0 + ty) * Hh + n0 + tx];
    }
    __syncthreads();
    #pragma unroll
    for (int r = 0; r < 4; ++r) {
        int ty = ty0 + r * 8;
        __nv_bfloat16 h, l; split2(t[tx][ty], h, l);
        size_t o = (size_t)(n0 + ty) * (2 * Ss) + k0 + tx;
        ob[o] = h; ob[o + Ss] = l;
    }
}

__global__ void __launch_bounds__(256)
softmax_split(const float* __restrict__ P, __nv_bfloat16* __restrict__ P2)
{
    const float* row = P + (size_t)blockIdx.x * Ss;
    __nv_bfloat16* orow = P2 + (size_t)blockIdx.x * (2 * Ss);
    int tid = threadIdx.x;
    float e[16];
    __shared__ float red[256];
    float m = -INFINITY;
    #pragma unroll
    for (int j4 = 0; j4 < 4; ++j4) {
        float4 v = *(const float4*)&row[tid * 16 + j4 * 4];
        e[j4*4+0]=v.x; e[j4*4+1]=v.y; e[j4*4+2]=v.z; e[j4*4+3]=v.w;
        m = fmaxf(m, fmaxf(fmaxf(v.x, v.y), fmaxf(v.z, v.w)));
    }
    red[tid] = m; __syncthreads();
    for (int s = 128; s > 0; s >>= 1) {
        if (tid < s) red[tid] = fmaxf(red[tid], red[tid + s]);
        __syncthreads();
    }
    m = red[0]; __syncthreads();
    float sum = 0.f;
    #pragma unroll
    for (int j = 0; j < 16; ++j) { e[j] = __expf(e[j] - m); sum += e[j]; }
    red[tid] = sum; __syncthreads();
    for (int s = 128; s > 0; s >>= 1) {
        if (tid < s) red[tid] += red[tid + s];
        __syncthreads();
    }
    float inv = 1.f / red[0];
    __nv_bfloat16 h[16], l[16];
    #pragma unroll
    for (int j = 0; j < 16; ++j) split2(e[j] * inv, h[j], l[j]);
    *(uint4*)&orow[tid * 16]          = make_uint4(pack2(h[0],h[1]), pack2(h[2],h[3]), pack2(h[4],h[5]), pack2(h[6],h[7]));
    *(uint4*)&orow[tid * 16 + 8]      = make_uint4(pack2(h[8],h[9]), pack2(h[10],h[11]), pack2(h[12],h[13]), pack2(h[14],h[15]));
    *(uint4*)&orow[Ss + tid * 16]     = make_uint4(pack2(l[0],l[1]), pack2(l[2],l[3]), pack2(l[4],l[5]), pack2(l[6],l[7]));
    *(uint4*)&orow[Ss + tid * 16 + 8] = make_uint4(pack2(l[8],l[9]), pack2(l[10],l[11]), pack2(l[12],l[13]), pack2(l[14],l[15]));
}

// ---------------- launch ----------------------------------------------------
extern "C" void kernel_launch(void* const* d_in, const int* in_sizes, int n_in,
                              void* d_out, int out_size)
{
    const float* hs   = (const float*)d_in[0];
    const float* wq   = (const float*)d_in[1];
    const float* wk   = (const float*)d_in[2];
    const float* wv   = (const float*)d_in[3];
    const float* wo   = (const float*)d_in[4];
    const float* fcos = (const float*)d_in[5];
    const float* fsin = (const float*)d_in[6];

    float* out = (float*)d_out;
    const long long T = (long long)Bb * Ss * Hh;
    float* out_o = out;
    float* out_k = out + T;
    float* out_v = out + 2 * T;

    float *p;
    __nv_bfloat16 *hs2, *w2, *qk2, *p2, *vt2, *ctx2;
    cudaGetSymbolAddress((void**)&p,    g_p);
    cudaGetSymbolAddress((void**)&hs2,  g_hs2);
    cudaGetSymbolAddress((void**)&w2,   g_w2);
    cudaGetSymbolAddress((void**)&qk2,  g_qk2);
    cudaGetSymbolAddress((void**)&p2,   g_p2);
    cudaGetSymbolAddress((void**)&vt2,  g_vt2);
    cudaGetSymbolAddress((void**)&ctx2, g_ctx2);

    cudaFuncSetAttribute(gemm3f<0>, cudaFuncAttributeMaxDynamicSharedMemorySize, GSMEM);
    cudaFuncSetAttribute(gemm3f<2>, cudaFuncAttributeMaxDynamicSharedMemorySize, GSMEM);
    cudaFuncSetAttribute(gemm3f<3>, cudaFuncAttributeMaxDynamicSharedMemorySize, GSMEM);

    dim3 blk(256);
    // input splits
    convert_split4<<<(unsigned)((size_t)Bb*Ss*Hh/1024), blk>>>(hs, hs2);
    convert_weights<<<dim3((unsigned)((size_t)Hh*Hh/1024), 1, 4), blk>>>(wq, wk, wv, wo, w2);

    // fused QKV projections (z = 0:q, 1:k, 2:v), RoPE in epilogue for q/k
    dim3 gqkv(Hh / BN, (Bb * Ss) / BM, 3);
    gemm3f<3><<<gqkv, 128, GSMEM>>>(hs2, w2, out_k, qk2, fcos, fsin,
                                    Bb*Ss, Hh, Hh,
                                    0, (long long)WSTRIDE, T, 1.f);

    // v transpose+split
    dim3 gtr(Hh / 32, Ss / 32, Bb);
    transpose_split<<<gtr, dim3(32, 8)>>>(out_v, vt2);

    // scores = 0.125 * Qr @ Kr^T (per batch)
    dim3 gsc(Ss / BN, Ss / BM, Bb);
    gemm3f<0><<<gsc, 128, GSMEM>>>(qk2, qk2 + QKSTRIDE, p, nullptr, nullptr, nullptr,
                                   Ss, Ss, Hh,
                                   (long long)Ss*2*Hh, (long long)Ss*2*Hh,
                                   (long long)Ss*Ss, SCALEF);

    // softmax + split
    softmax_split<<<Bb * Ss, blk>>>(p, p2);

    // ctx = P @ V (per batch), split fused -> ctx2
    dim3 gcx(Hh / BN, Ss / BM, Bb);
    gemm3f<2><<<gcx, 128, GSMEM>>>(p2, vt2, nullptr, ctx2, nullptr, nullptr,
                                   Ss, Hh, Ss,
                                   (long long)Ss*2*Ss, (long long)Hh*2*Ss,
                                   (long long)Ss*2*Hh, 1.f);

    // output projection
    dim3 gop(Hh / BN, (Bb * Ss) / BM, 1);
    gemm3f<0><<<gop, 128, GSMEM>>>(ctx2, w2 + 3 * WSTRIDE, out_o, nullptr, nullptr, nullptr,
                                   Bb*Ss, Hh, Hh, 0, 0, 0, 1.f);
}